// round 13
// baseline (speedup 1.0000x reference)
#include <cuda_runtime.h>
#include <math.h>

#define Bc   32
#define Tc   256
#define Fc   32
#define HIDc 128
#define ZW   640
#define Vc   101
#define LBLc 32
#define NEGF (-1e30f)

#define NCTA 128
#define NTHR 256
#define WSTRIDE 2564                 // per-cg weight stride in floats (16B-aligned)
#define HSTRIDE 258                  // per-row dup-h stride (8B-aligned, conflict-free)
#define SW_FLOATS (8*WSTRIDE)
#define SH_FLOATS (72*HSTRIDE)
#define SC_FLOATS (2*8*64*2)
#define SMEM_BYTES ((SW_FLOATS+SH_FLOATS+SC_FLOATS)*4)

// ---------------------------------------------------------------------------
// Device scratch.
// ---------------------------------------------------------------------------
__device__ __align__(16) float g_h[2][Fc][Bc][HIDc];
__device__ __align__(16) float g_c[2][Fc][Bc][HIDc];
__device__ __align__(16) float g_feat[Bc][Tc][HIDc];
__device__ __align__(16) float g_logp[Bc][Tc][Vc];
__device__ unsigned g_cnt4[4 * 32];
__device__ unsigned g_gen4[4 * 32];

__device__ __forceinline__ float fsig(float x) {
    return __fdividef(1.0f, 1.0f + __expf(-x));
}
__device__ __forceinline__ float ftanh(float x) {
    return 1.0f - __fdividef(2.0f, __expf(2.0f * x) + 1.0f);
}

__device__ __forceinline__ unsigned long long pack2f(float lo, float hi) {
    unsigned long long r;
    asm("mov.b64 %0, {%1, %2};" : "=l"(r) : "f"(lo), "f"(hi));
    return r;
}
__device__ __forceinline__ void unpack2f(unsigned long long v, float& lo, float& hi) {
    asm("mov.b64 {%0, %1}, %2;" : "=f"(lo), "=f"(hi) : "l"(v));
}
__device__ __forceinline__ unsigned long long fma2(unsigned long long a,
                                                   unsigned long long b,
                                                   unsigned long long c) {
    unsigned long long d;
    asm("fma.rn.f32x2 %0, %1, %2, %3;" : "=l"(d) : "l"(a), "l"(b), "l"(c));
    return d;
}

__global__ void init_kernel() {
    const int nh = 2 * Fc * Bc * HIDc;
    float* ph = &g_h[0][0][0][0];
    float* pc = &g_c[0][0][0][0];
    for (int i = blockIdx.x * blockDim.x + threadIdx.x; i < nh;
         i += gridDim.x * blockDim.x) { ph[i] = 0.0f; pc[i] = 0.0f; }
    const int nf = Bc * Tc * HIDc;
    float* pf = &g_feat[0][0][0];
    for (int i = blockIdx.x * blockDim.x + threadIdx.x; i < nf;
         i += gridDim.x * blockDim.x) pf[i] = 0.0f;
    if (blockIdx.x == 0 && threadIdx.x < 4 * 32) {
        g_cnt4[threadIdx.x] = 0u;
        g_gen4[threadIdx.x] = 0u;
    }
}

// Per-bg grid barrier (32 CTAs).
__device__ __forceinline__ void gbar(int it, int bg) {
    __syncthreads();
    if (threadIdx.x == 0) {
        unsigned* cnt = &g_cnt4[bg * 32];
        unsigned* gen = &g_gen4[bg * 32];
        const unsigned target = (unsigned)(it + 1);
        unsigned old;
        asm volatile("atom.acq_rel.gpu.global.add.u32 %0, [%1], %2;"
                     : "=r"(old) : "l"(cnt), "r"(1u) : "memory");
        if (old == target * 32u - 1u) {
            asm volatile("st.release.gpu.global.u32 [%0], %1;"
                         :: "l"(gen), "r"(target) : "memory");
        } else {
            unsigned cur;
            do {
                asm volatile("ld.acquire.gpu.global.u32 %0, [%1];"
                             : "=r"(cur) : "l"(gen) : "memory");
            } while (cur < target);
        }
    }
    __syncthreads();
}

// ---------------------------------------------------------------------------
// Persistent MDLSTM wavefront (R12 + batched staging LDGs).
// 128 CTAs = 8 jkb x 4 bg x 4 cgid, 256 threads (2 warps/SMSP).
// ---------------------------------------------------------------------------
__global__ __launch_bounds__(NTHR, 1)
void mdlstm_persist(const float* __restrict__ X,
                    const float* __restrict__ Wx,
                    const float* __restrict__ Wh1,
                    const float* __restrict__ Wh2,
                    const float* __restrict__ bias)
{
    extern __shared__ float smem[];
    float* s_w  = smem;
    float* s_h2 = smem + SW_FLOATS;
    float* s_c  = smem + SW_FLOATS + SH_FLOATS;

    const int tid  = threadIdx.x;
    const int bx   = blockIdx.x;
    const int jkb  = bx & 7;
    const int bg   = (bx >> 3) & 3;
    const int cgid = bx >> 5;

    const int half = tid >> 7;
    const int cg   = (tid >> 4) & 7;
    const int rg   = tid & 15;

    // One-time: recurrent weights into smem.
    for (int i = tid; i < 8 * 5 * 256 * 2; i += NTHR) {
        int c   = i & 1;
        int k   = (i >> 1) & 255;
        int t2  = i >> 9;
        int g   = t2 % 5;
        int cgl = t2 / 5;
        int col = g * HIDc + jkb * 16 + cgl * 2 + c;
        float v = (k < 128) ? Wh1[k * ZW + col] : Wh2[(k - 128) * ZW + col];
        s_w[cgl * WSTRIDE + ((g << 8) + k) * 2 + c] = v;
    }

    const int kk0 = jkb * 16 + cg * 2;
    float wxl[5], wxh[5], bl0[5], bl1[5];
#pragma unroll
    for (int g = 0; g < 5; g++) {
        int col = g * HIDc + kk0;
        wxl[g] = Wx[col];  wxh[g] = Wx[col + 1];
        bl0[g] = bias[col]; bl1[g] = bias[col + 1];
    }

    int rowj[2], cellj[2], bbj[2];
    rowj[0] = rg + 32 * half;
    rowj[1] = rowj[0] + 16;
#pragma unroll
    for (int j = 0; j < 2; j++) {
        cellj[j] = cgid * 8 + (rowj[j] >> 3);
        bbj[j]   = bg * 8 + (rowj[j] & 7);
    }

    const float* wp  = s_w + cg * WSTRIDE;
    const float* up0 = s_h2 + rowj[0] * HSTRIDE;
    const float* up1 = s_h2 + rowj[1] * HSTRIDE;
    const float* lf0 = up0 + 8 * HSTRIDE;
    const float* lf1 = up1 + 8 * HSTRIDE;

    // Staging decomposition: exactly 9 chunks per thread (72*32/256).
    int st_rr[9], st_kq[9], st_bb[9];
#pragma unroll
    for (int j = 0; j < 9; j++) {
        int i = tid + j * NTHR;
        st_rr[j] = i >> 5;
        st_kq[j] = (i & 31) << 2;
        st_bb[j] = bg * 8 + (st_rr[j] & 7);
    }

    float2 c_reg[2] = {make_float2(0.f, 0.f), make_float2(0.f, 0.f)};

    __syncthreads();

    for (int d = 0; d < Tc + Fc - 1; d++) {
        const int h_lo = (d > Tc - 1) ? d - (Tc - 1) : 0;
        const int h_hi = (d < Fc - 1) ? d : (Fc - 1);
        const int ncells = h_hi - h_lo + 1;
        const int rd = (d + 1) & 1, wr = d & 1;
        const bool regB = (d > Tc - 1);

        bool val[2]; int hh[2], ww[2];
#pragma unroll
        for (int j = 0; j < 2; j++) {
            val[j] = cellj[j] < ncells;
            hh[j]  = h_lo + cellj[j];
            ww[j]  = d - hh[j];
        }

        // ---- Issue ALL staging LDG.128s first (MLP=9), then overlap math ----
        float4 sv[9];
#pragma unroll
        for (int j = 0; j < 9; j++) {
            int hhs = h_lo + cgid * 8 - 1 + (st_rr[j] >> 3);
            if (hhs >= 0 && hhs < Fc)
                sv[j] = __ldcg((const float4*)&g_h[rd][hhs][st_bb[j]][st_kq[j]]);
            else
                sv[j] = make_float4(0.f, 0.f, 0.f, 0.f);
        }

        // Boundary c prefetch + X prefetch (in LDG shadow).
        float2 cbnd = make_float2(0.f, 0.f);
        if (!regB) {
            if (rowj[0] < 8 && val[0] && hh[0] > 0)
                cbnd = __ldcg((const float2*)&g_c[rd][hh[0] - 1][bbj[0]][kk0]);
        } else {
            if (rowj[1] >= 56 && val[1])
                cbnd = __ldcg((const float2*)&g_c[rd][hh[1]][bbj[1]][kk0]);
        }
        float xv[2];
#pragma unroll
        for (int j = 0; j < 2; j++)
            xv[j] = val[j] ? __ldg(&X[bbj[j] * (Tc * Fc) + ww[j] * Fc + hh[j]]) : 0.f;

        // z0 = x*Wx + bias (also in LDG shadow).
        unsigned long long acc[2][5];
#pragma unroll
        for (int j = 0; j < 2; j++)
#pragma unroll
            for (int g = 0; g < 5; g++)
                acc[j][g] = pack2f(fmaf(xv[j], wxl[g], bl0[g]),
                                   fmaf(xv[j], wxh[g], bl1[g]));

        // Duplicate-pair stores.
#pragma unroll
        for (int j = 0; j < 9; j++) {
            float* dst = s_h2 + st_rr[j] * HSTRIDE + st_kq[j] * 2;
            *(float2*)(dst)     = make_float2(sv[j].x, sv[j].x);
            *(float2*)(dst + 2) = make_float2(sv[j].y, sv[j].y);
            *(float2*)(dst + 4) = make_float2(sv[j].z, sv[j].z);
            *(float2*)(dst + 6) = make_float2(sv[j].w, sv[j].w);
        }
        __syncthreads();

        // z += h_left @ Wh1
#pragma unroll 2
        for (int k2 = 0; k2 < 64; k2++) {
            ulonglong2 wv[5];
#pragma unroll
            for (int g = 0; g < 5; g++)
                wv[g] = *(const ulonglong2*)(wp + ((g << 8) + 2 * k2) * 2);
            unsigned long long h0a = *(const unsigned long long*)(lf0 + 4 * k2);
            unsigned long long h0b = *(const unsigned long long*)(lf0 + 4 * k2 + 2);
            unsigned long long h1a = *(const unsigned long long*)(lf1 + 4 * k2);
            unsigned long long h1b = *(const unsigned long long*)(lf1 + 4 * k2 + 2);
#pragma unroll
            for (int g = 0; g < 5; g++) {
                acc[0][g] = fma2(wv[g].x, h0a, acc[0][g]);
                acc[1][g] = fma2(wv[g].x, h1a, acc[1][g]);
            }
#pragma unroll
            for (int g = 0; g < 5; g++) {
                acc[0][g] = fma2(wv[g].y, h0b, acc[0][g]);
                acc[1][g] = fma2(wv[g].y, h1b, acc[1][g]);
            }
        }
        // z += h_up @ Wh2
#pragma unroll 2
        for (int k2 = 0; k2 < 64; k2++) {
            ulonglong2 wv[5];
#pragma unroll
            for (int g = 0; g < 5; g++)
                wv[g] = *(const ulonglong2*)(wp + ((g << 8) + 128 + 2 * k2) * 2);
            unsigned long long h0a = *(const unsigned long long*)(up0 + 4 * k2);
            unsigned long long h0b = *(const unsigned long long*)(up0 + 4 * k2 + 2);
            unsigned long long h1a = *(const unsigned long long*)(up1 + 4 * k2);
            unsigned long long h1b = *(const unsigned long long*)(up1 + 4 * k2 + 2);
#pragma unroll
            for (int g = 0; g < 5; g++) {
                acc[0][g] = fma2(wv[g].x, h0a, acc[0][g]);
                acc[1][g] = fma2(wv[g].x, h1a, acc[1][g]);
            }
#pragma unroll
            for (int g = 0; g < 5; g++) {
                acc[0][g] = fma2(wv[g].y, h0b, acc[0][g]);
                acc[1][g] = fma2(wv[g].y, h1b, acc[1][g]);
            }
        }

        // Gates (z order: i, g, f1, f2, o).
#pragma unroll
        for (int j = 0; j < 2; j++) {
            if (!val[j]) continue;
            float zi0, zi1, zg0, zg1, za0, za1, zb0, zb1, zo0, zo1;
            unpack2f(acc[j][0], zi0, zi1);
            unpack2f(acc[j][1], zg0, zg1);
            unpack2f(acc[j][2], za0, za1);
            unpack2f(acc[j][3], zb0, zb1);
            unpack2f(acc[j][4], zo0, zo1);
            const int H = hh[j], W = ww[j], B = bbj[j];
            const int row = rowj[j];

            float2 cl, cu;
            if (!regB) {
                cl = c_reg[j];
                if (row >= 8)
                    cu = *(const float2*)&s_c[(((rd * 8 + cg) * 64) + row - 8) * 2];
                else
                    cu = (H > 0) ? cbnd : make_float2(0.f, 0.f);
            } else {
                cu = c_reg[j];
                if (row < 56)
                    cl = *(const float2*)&s_c[(((rd * 8 + cg) * 64) + row + 8) * 2];
                else
                    cl = cbnd;
            }

            float cA = fsig(za0) * cl.x + fsig(zb0) * cu.x + fsig(zi0) * ftanh(zg0);
            float cB = fsig(za1) * cl.y + fsig(zb1) * cu.y + fsig(zi1) * ftanh(zg1);
            float hA = fsig(zo0) * ftanh(cA);
            float hB = fsig(zo1) * ftanh(cB);

            c_reg[j] = make_float2(cA, cB);
            *(float2*)&s_c[(((wr * 8 + cg) * 64) + row) * 2] = make_float2(cA, cB);
            if (row < 8 || row >= 56)
                __stcg((float2*)&g_c[wr][H][B][kk0], make_float2(cA, cB));
            __stcg((float2*)&g_h[wr][H][B][kk0], make_float2(hA, hB));

            atomicAdd(&g_feat[B][W][kk0],     hA);
            atomicAdd(&g_feat[B][W][kk0 + 1], hB);
        }

        gbar(d, bg);
    }
}

// ---------------------------------------------------------------------------
// FC + log-softmax (validated R8 version).
// ---------------------------------------------------------------------------
#define FCW 8
#define FC_SMEM ((HIDc*Vc + FCW*HIDc) * 4)
__global__ __launch_bounds__(128)
void fc_kernel(const float* __restrict__ W_fc, const float* __restrict__ b_fc)
{
    extern __shared__ float fsm[];
    float* s_wfc = fsm;
    float* s_f   = fsm + HIDc * Vc;

    const int wt = blockIdx.x, b = blockIdx.y, tid = threadIdx.x;
    const int wid = tid >> 5, lid = tid & 31;

    for (int i = tid; i < HIDc * Vc; i += 128) s_wfc[i] = W_fc[i];
    for (int i = tid; i < FCW * HIDc; i += 128)
        s_f[i] = g_feat[b][wt * FCW + (i >> 7)][i & 127];
    __syncthreads();

    for (int ws = 0; ws < 2; ws++) {
        const int wloc = wid * 2 + ws;
        const int w = wt * FCW + wloc;
        const float* f = s_f + wloc * HIDc;
        float lg[4];
#pragma unroll
        for (int i = 0; i < 4; i++) {
            int col = lid + 32 * i;
            float a = (col < Vc) ? b_fc[col] : NEGF;
            if (col < Vc) {
#pragma unroll 8
                for (int k = 0; k < HIDc; k++)
                    a = fmaf(f[k], s_wfc[k * Vc + col], a);
            }
            lg[i] = a;
        }
        float m = fmaxf(fmaxf(lg[0], lg[1]), fmaxf(lg[2], lg[3]));
#pragma unroll
        for (int o = 16; o > 0; o >>= 1)
            m = fmaxf(m, __shfl_xor_sync(0xffffffff, m, o));
        float s = 0.f;
#pragma unroll
        for (int i = 0; i < 4; i++) s += __expf(lg[i] - m);
#pragma unroll
        for (int o = 16; o > 0; o >>= 1)
            s += __shfl_xor_sync(0xffffffff, s, o);
        float lse = m + __logf(s);
#pragma unroll
        for (int i = 0; i < 4; i++) {
            int col = lid + 32 * i;
            if (col < Vc) g_logp[b][w][col] = lg[i] - lse;
        }
    }
}

// ---------------------------------------------------------------------------
// CTC alpha: one warp per batch; prefetch depth 4 so L2 latency (~600cyc)
// sits fully inside 3 iterations of compute slack.
// ---------------------------------------------------------------------------
__global__ __launch_bounds__(32)
void ctc_kernel(const int* __restrict__ y, float* __restrict__ out)
{
    const int b = blockIdx.x, l = threadIdx.x;
    const int lbl = y[b * LBLc + l];
    const int lblp = __shfl_up_sync(0xffffffffu, lbl, 1);
    const bool sk = (l > 0) && (lbl != lblp);
    const float* lp = &g_logp[b][0][0];

    float a0 = (l == 0) ? lp[Vc - 1] : NEGF;
    float a1 = (l == 0) ? lp[lbl]    : NEGF;
    float a2 = NEGF;

    float pb[4], py[4];
#pragma unroll
    for (int j = 0; j < 4; j++) {
        pb[j] = __ldcg(&lp[Vc * (1 + j) + (Vc - 1)]);
        py[j] = __ldcg(&lp[Vc * (1 + j) + lbl]);
    }

    for (int t = 1; t < Tc; t++) {
        const float lpb = pb[0], lpy = py[0];
#pragma unroll
        for (int j = 0; j < 3; j++) { pb[j] = pb[j + 1]; py[j] = py[j + 1]; }
        if (t + 4 < Tc) {
            pb[3] = __ldcg(&lp[Vc * (t + 4) + (Vc - 1)]);
            py[3] = __ldcg(&lp[Vc * (t + 4) + lbl]);
        }
        float pa1 = __shfl_up_sync(0xffffffffu, a1, 1);
        if (l == 0) pa1 = NEGF;

        float m0 = fmaxf(a0, pa1);
        float n0 = m0 + __logf(__expf(a0 - m0) + __expf(pa1 - m0)) + lpb;

        float s2 = sk ? pa1 : NEGF;
        float m1 = fmaxf(a1, fmaxf(a0, s2));
        float n1 = m1 + __logf(__expf(a1 - m1) + __expf(a0 - m1) +
                               __expf(s2 - m1)) + lpy;

        float n2 = a2;
        if (l == 31) {
            float m2 = fmaxf(a2, a1);
            n2 = m2 + __logf(__expf(a2 - m2) + __expf(a1 - m2)) + lpb;
        }
        a0 = n0; a1 = n1; a2 = n2;
    }

    if (l == 31) {
        float m = fmaxf(a2, a1);
        out[b] = -(m + __logf(__expf(a2 - m) + __expf(a1 - m)));
    }
}

// ---------------------------------------------------------------------------
// Inputs: X, y, Wx, Wh1, Wh2, b, W_fc, b_fc. Output: float[32].
// ---------------------------------------------------------------------------
extern "C" void kernel_launch(void* const* d_in, const int* in_sizes, int n_in,
                              void* d_out, int out_size)
{
    const float* X    = (const float*)d_in[0];
    const int*   y    = (const int*)  d_in[1];
    const float* Wx   = (const float*)d_in[2];
    const float* Wh1  = (const float*)d_in[3];
    const float* Wh2  = (const float*)d_in[4];
    const float* bias = (const float*)d_in[5];
    const float* W_fc = (const float*)d_in[6];
    const float* b_fc = (const float*)d_in[7];
    float* out = (float*)d_out;

    cudaFuncSetAttribute(mdlstm_persist,
                         cudaFuncAttributeMaxDynamicSharedMemorySize, SMEM_BYTES);
    cudaFuncSetAttribute(fc_kernel,
                         cudaFuncAttributeMaxDynamicSharedMemorySize, FC_SMEM);

    init_kernel<<<256, 256>>>();
    mdlstm_persist<<<NCTA, NTHR, SMEM_BYTES>>>(X, Wx, Wh1, Wh2, bias);
    fc_kernel<<<dim3(Tc / FCW, Bc), 128, FC_SMEM>>>(W_fc, b_fc);
    ctc_kernel<<<Bc, 32>>>(y, out);
}

// round 14
// speedup vs baseline: 1.0812x; 1.0812x over previous
#include <cuda_runtime.h>
#include <math.h>

#define Bc   32
#define Tc   256
#define Fc   32
#define HIDc 128
#define ZW   640
#define Vc   101
#define LBLc 32
#define NEGF (-1e30f)

#define NCTA 128
#define NTHR 256
#define WSTRIDE 2564                 // per-cg weight stride in floats (16B-aligned)
#define HSTRIDE 258                  // per-row dup-h stride (8B-aligned, conflict-free)
#define SW_FLOATS (8*WSTRIDE)
#define SH_FLOATS (72*HSTRIDE)
#define SC_FLOATS (2*8*64*2)
#define SMEM_BYTES ((SW_FLOATS+SH_FLOATS+SC_FLOATS)*4)

// ---------------------------------------------------------------------------
// Device scratch.
// ---------------------------------------------------------------------------
__device__ __align__(16) float g_h[2][Fc][Bc][HIDc];
__device__ __align__(16) float g_c[2][Fc][Bc][HIDc];
__device__ __align__(16) float g_feat[Bc][Tc][HIDc];
__device__ __align__(16) float g_logp[Bc][Tc][Vc];
__device__ unsigned g_cnt4[4 * 32];
__device__ unsigned g_gen4[4 * 32];

__device__ __forceinline__ float fsig(float x) {
    return __fdividef(1.0f, 1.0f + __expf(-x));
}
__device__ __forceinline__ float ftanh(float x) {
    return 1.0f - __fdividef(2.0f, __expf(2.0f * x) + 1.0f);
}

__device__ __forceinline__ unsigned long long pack2f(float lo, float hi) {
    unsigned long long r;
    asm("mov.b64 %0, {%1, %2};" : "=l"(r) : "f"(lo), "f"(hi));
    return r;
}
__device__ __forceinline__ void unpack2f(unsigned long long v, float& lo, float& hi) {
    asm("mov.b64 {%0, %1}, %2;" : "=f"(lo), "=f"(hi) : "l"(v));
}
__device__ __forceinline__ unsigned long long fma2(unsigned long long a,
                                                   unsigned long long b,
                                                   unsigned long long c) {
    unsigned long long d;
    asm("fma.rn.f32x2 %0, %1, %2, %3;" : "=l"(d) : "l"(a), "l"(b), "l"(c));
    return d;
}

__global__ void init_kernel() {
    const int nh = 2 * Fc * Bc * HIDc;
    float* ph = &g_h[0][0][0][0];
    float* pc = &g_c[0][0][0][0];
    for (int i = blockIdx.x * blockDim.x + threadIdx.x; i < nh;
         i += gridDim.x * blockDim.x) { ph[i] = 0.0f; pc[i] = 0.0f; }
    const int nf = Bc * Tc * HIDc;
    float* pf = &g_feat[0][0][0];
    for (int i = blockIdx.x * blockDim.x + threadIdx.x; i < nf;
         i += gridDim.x * blockDim.x) pf[i] = 0.0f;
    if (blockIdx.x == 0 && threadIdx.x < 4 * 32) {
        g_cnt4[threadIdx.x] = 0u;
        g_gen4[threadIdx.x] = 0u;
    }
}

// Split per-bg grid barrier (32 CTAs):
//   arrive: block-sync then one release-counted atomic; 32nd arrival of a
//           diagonal publishes gen = arrivals/32.
//   wait:   every lane acquire-spins (own acquire -> orders its later reads).
__device__ __forceinline__ void gbar_arrive(int bg) {
    __syncthreads();
    if (threadIdx.x == 0) {
        unsigned old;
        asm volatile("atom.acq_rel.gpu.global.add.u32 %0, [%1], %2;"
                     : "=r"(old) : "l"(&g_cnt4[bg * 32]), "r"(1u) : "memory");
        unsigned done = old + 1u;
        if ((done & 31u) == 0u) {
            asm volatile("st.release.gpu.global.u32 [%0], %1;"
                         :: "l"(&g_gen4[bg * 32]), "r"(done >> 5) : "memory");
        }
    }
}
__device__ __forceinline__ void gbar_wait(unsigned target, int bg) {
    const unsigned* gen = &g_gen4[bg * 32];
    unsigned cur;
    do {
        asm volatile("ld.acquire.gpu.global.u32 %0, [%1];"
                     : "=r"(cur) : "l"(gen) : "memory");
    } while (cur < target);
}

// ---------------------------------------------------------------------------
// Persistent MDLSTM wavefront (R12 base + split barrier with pre-wait work).
// 128 CTAs = 8 jkb x 4 bg x 4 cgid, 256 threads (2 warps/SMSP).
// Thread (half, cg, rg) owns 2 rows x (2 k-cols x 5 gates); c in regs + smem.
// ---------------------------------------------------------------------------
__global__ __launch_bounds__(NTHR, 1)
void mdlstm_persist(const float* __restrict__ X,
                    const float* __restrict__ Wx,
                    const float* __restrict__ Wh1,
                    const float* __restrict__ Wh2,
                    const float* __restrict__ bias)
{
    extern __shared__ float smem[];
    float* s_w  = smem;
    float* s_h2 = smem + SW_FLOATS;
    float* s_c  = smem + SW_FLOATS + SH_FLOATS;

    const int tid  = threadIdx.x;
    const int bx   = blockIdx.x;
    const int jkb  = bx & 7;
    const int bg   = (bx >> 3) & 3;
    const int cgid = bx >> 5;

    const int half = tid >> 7;
    const int cg   = (tid >> 4) & 7;
    const int rg   = tid & 15;

    // One-time: recurrent weights into smem.
    for (int i = tid; i < 8 * 5 * 256 * 2; i += NTHR) {
        int c   = i & 1;
        int k   = (i >> 1) & 255;
        int t2  = i >> 9;
        int g   = t2 % 5;
        int cgl = t2 / 5;
        int col = g * HIDc + jkb * 16 + cgl * 2 + c;
        float v = (k < 128) ? Wh1[k * ZW + col] : Wh2[(k - 128) * ZW + col];
        s_w[cgl * WSTRIDE + ((g << 8) + k) * 2 + c] = v;
    }

    const int kk0 = jkb * 16 + cg * 2;
    float wxl[5], wxh[5], bl0[5], bl1[5];
#pragma unroll
    for (int g = 0; g < 5; g++) {
        int col = g * HIDc + kk0;
        wxl[g] = Wx[col];  wxh[g] = Wx[col + 1];
        bl0[g] = bias[col]; bl1[g] = bias[col + 1];
    }

    int rowj[2], cellj[2], bbj[2];
    rowj[0] = rg + 32 * half;
    rowj[1] = rowj[0] + 16;
#pragma unroll
    for (int j = 0; j < 2; j++) {
        cellj[j] = cgid * 8 + (rowj[j] >> 3);
        bbj[j]   = bg * 8 + (rowj[j] & 7);
    }

    const float* wp  = s_w + cg * WSTRIDE;
    const float* up0 = s_h2 + rowj[0] * HSTRIDE;
    const float* up1 = s_h2 + rowj[1] * HSTRIDE;
    const float* lf0 = up0 + 8 * HSTRIDE;
    const float* lf1 = up1 + 8 * HSTRIDE;

    float2 c_reg[2] = {make_float2(0.f, 0.f), make_float2(0.f, 0.f)};

    __syncthreads();

    for (int d = 0; d < Tc + Fc - 1; d++) {
        const int h_lo = (d > Tc - 1) ? d - (Tc - 1) : 0;
        const int h_hi = (d < Fc - 1) ? d : (Fc - 1);
        const int ncells = h_hi - h_lo + 1;
        const int rd = (d + 1) & 1, wr = d & 1;
        const bool regB = (d > Tc - 1);

        bool val[2]; int hh[2], ww[2];
#pragma unroll
        for (int j = 0; j < 2; j++) {
            val[j] = cellj[j] < ncells;
            hh[j]  = h_lo + cellj[j];
            ww[j]  = d - hh[j];
        }

        // ---- Peer-independent work BEFORE the barrier wait ----
        float xv[2];
#pragma unroll
        for (int j = 0; j < 2; j++)
            xv[j] = val[j] ? __ldg(&X[bbj[j] * (Tc * Fc) + ww[j] * Fc + hh[j]]) : 0.f;

        unsigned long long acc[2][5];
#pragma unroll
        for (int j = 0; j < 2; j++)
#pragma unroll
            for (int g = 0; g < 5; g++)
                acc[j][g] = pack2f(fmaf(xv[j], wxl[g], bl0[g]),
                                   fmaf(xv[j], wxh[g], bl1[g]));

        // ---- Wait for previous diagonal's h/c writes (gen == d) ----
        if (d > 0) gbar_wait((unsigned)d, bg);

        // Boundary c prefetch (reads peer CTA's previous-diagonal write).
        float2 cbnd = make_float2(0.f, 0.f);
        if (!regB) {
            if (rowj[0] < 8 && val[0] && hh[0] > 0)
                cbnd = __ldcg((const float2*)&g_c[rd][hh[0] - 1][bbj[0]][kk0]);
        } else {
            if (rowj[1] >= 56 && val[1])
                cbnd = __ldcg((const float2*)&g_c[rd][hh[1]][bbj[1]][kk0]);
        }

        // Stage 9 state rows x 8 batches as duplicate pairs.
        for (int i = tid; i < 72 * 32; i += NTHR) {
            int rr  = i >> 5;
            int kq  = (i & 31) << 2;
            int hhs = h_lo + cgid * 8 - 1 + (rr >> 3);
            int bb2 = bg * 8 + (rr & 7);
            float4 v = make_float4(0.f, 0.f, 0.f, 0.f);
            if (hhs >= 0 && hhs < Fc)
                v = __ldcg((const float4*)&g_h[rd][hhs][bb2][kq]);
            float* dst = s_h2 + rr * HSTRIDE + kq * 2;
            *(float2*)(dst)     = make_float2(v.x, v.x);
            *(float2*)(dst + 2) = make_float2(v.y, v.y);
            *(float2*)(dst + 4) = make_float2(v.z, v.z);
            *(float2*)(dst + 6) = make_float2(v.w, v.w);
        }
        __syncthreads();

        // z += h_left @ Wh1
#pragma unroll 2
        for (int k2 = 0; k2 < 64; k2++) {
            ulonglong2 wv[5];
#pragma unroll
            for (int g = 0; g < 5; g++)
                wv[g] = *(const ulonglong2*)(wp + ((g << 8) + 2 * k2) * 2);
            unsigned long long h0a = *(const unsigned long long*)(lf0 + 4 * k2);
            unsigned long long h0b = *(const unsigned long long*)(lf0 + 4 * k2 + 2);
            unsigned long long h1a = *(const unsigned long long*)(lf1 + 4 * k2);
            unsigned long long h1b = *(const unsigned long long*)(lf1 + 4 * k2 + 2);
#pragma unroll
            for (int g = 0; g < 5; g++) {
                acc[0][g] = fma2(wv[g].x, h0a, acc[0][g]);
                acc[1][g] = fma2(wv[g].x, h1a, acc[1][g]);
            }
#pragma unroll
            for (int g = 0; g < 5; g++) {
                acc[0][g] = fma2(wv[g].y, h0b, acc[0][g]);
                acc[1][g] = fma2(wv[g].y, h1b, acc[1][g]);
            }
        }
        // z += h_up @ Wh2
#pragma unroll 2
        for (int k2 = 0; k2 < 64; k2++) {
            ulonglong2 wv[5];
#pragma unroll
            for (int g = 0; g < 5; g++)
                wv[g] = *(const ulonglong2*)(wp + ((g << 8) + 128 + 2 * k2) * 2);
            unsigned long long h0a = *(const unsigned long long*)(up0 + 4 * k2);
            unsigned long long h0b = *(const unsigned long long*)(up0 + 4 * k2 + 2);
            unsigned long long h1a = *(const unsigned long long*)(up1 + 4 * k2);
            unsigned long long h1b = *(const unsigned long long*)(up1 + 4 * k2 + 2);
#pragma unroll
            for (int g = 0; g < 5; g++) {
                acc[0][g] = fma2(wv[g].x, h0a, acc[0][g]);
                acc[1][g] = fma2(wv[g].x, h1a, acc[1][g]);
            }
#pragma unroll
            for (int g = 0; g < 5; g++) {
                acc[0][g] = fma2(wv[g].y, h0b, acc[0][g]);
                acc[1][g] = fma2(wv[g].y, h1b, acc[1][g]);
            }
        }

        // Gates (z order: i, g, f1, f2, o).
#pragma unroll
        for (int j = 0; j < 2; j++) {
            if (!val[j]) continue;
            float zi0, zi1, zg0, zg1, za0, za1, zb0, zb1, zo0, zo1;
            unpack2f(acc[j][0], zi0, zi1);
            unpack2f(acc[j][1], zg0, zg1);
            unpack2f(acc[j][2], za0, za1);
            unpack2f(acc[j][3], zb0, zb1);
            unpack2f(acc[j][4], zo0, zo1);
            const int H = hh[j], W = ww[j], B = bbj[j];
            const int row = rowj[j];

            float2 cl, cu;
            if (!regB) {
                cl = c_reg[j];
                if (row >= 8)
                    cu = *(const float2*)&s_c[(((rd * 8 + cg) * 64) + row - 8) * 2];
                else
                    cu = (H > 0) ? cbnd : make_float2(0.f, 0.f);
            } else {
                cu = c_reg[j];
                if (row < 56)
                    cl = *(const float2*)&s_c[(((rd * 8 + cg) * 64) + row + 8) * 2];
                else
                    cl = cbnd;
            }

            float cA = fsig(za0) * cl.x + fsig(zb0) * cu.x + fsig(zi0) * ftanh(zg0);
            float cB = fsig(za1) * cl.y + fsig(zb1) * cu.y + fsig(zi1) * ftanh(zg1);
            float hA = fsig(zo0) * ftanh(cA);
            float hB = fsig(zo1) * ftanh(cB);

            c_reg[j] = make_float2(cA, cB);
            *(float2*)&s_c[(((wr * 8 + cg) * 64) + row) * 2] = make_float2(cA, cB);
            if (row < 8 || row >= 56)
                __stcg((float2*)&g_c[wr][H][B][kk0], make_float2(cA, cB));
            __stcg((float2*)&g_h[wr][H][B][kk0], make_float2(hA, hB));

            atomicAdd(&g_feat[B][W][kk0],     hA);
            atomicAdd(&g_feat[B][W][kk0 + 1], hB);
        }

        gbar_arrive(bg);
    }
}

// ---------------------------------------------------------------------------
// FC + log-softmax (validated R8/R12 version).
// ---------------------------------------------------------------------------
#define FCW 8
#define FC_SMEM ((HIDc*Vc + FCW*HIDc) * 4)
__global__ __launch_bounds__(128)
void fc_kernel(const float* __restrict__ W_fc, const float* __restrict__ b_fc)
{
    extern __shared__ float fsm[];
    float* s_wfc = fsm;
    float* s_f   = fsm + HIDc * Vc;

    const int wt = blockIdx.x, b = blockIdx.y, tid = threadIdx.x;
    const int wid = tid >> 5, lid = tid & 31;

    for (int i = tid; i < HIDc * Vc; i += 128) s_wfc[i] = W_fc[i];
    for (int i = tid; i < FCW * HIDc; i += 128)
        s_f[i] = g_feat[b][wt * FCW + (i >> 7)][i & 127];
    __syncthreads();

    for (int ws = 0; ws < 2; ws++) {
        const int wloc = wid * 2 + ws;
        const int w = wt * FCW + wloc;
        const float* f = s_f + wloc * HIDc;
        float lg[4];
#pragma unroll
        for (int i = 0; i < 4; i++) {
            int col = lid + 32 * i;
            float a = (col < Vc) ? b_fc[col] : NEGF;
            if (col < Vc) {
#pragma unroll 8
                for (int k = 0; k < HIDc; k++)
                    a = fmaf(f[k], s_wfc[k * Vc + col], a);
            }
            lg[i] = a;
        }
        float m = fmaxf(fmaxf(lg[0], lg[1]), fmaxf(lg[2], lg[3]));
#pragma unroll
        for (int o = 16; o > 0; o >>= 1)
            m = fmaxf(m, __shfl_xor_sync(0xffffffff, m, o));
        float s = 0.f;
#pragma unroll
        for (int i = 0; i < 4; i++) s += __expf(lg[i] - m);
#pragma unroll
        for (int o = 16; o > 0; o >>= 1)
            s += __shfl_xor_sync(0xffffffff, s, o);
        float lse = m + __logf(s);
#pragma unroll
        for (int i = 0; i < 4; i++) {
            int col = lid + 32 * i;
            if (col < Vc) g_logp[b][w][col] = lg[i] - lse;
        }
    }
}

// ---------------------------------------------------------------------------
// CTC alpha: one warp per batch (validated R12 version, depth-2 prefetch).
// ---------------------------------------------------------------------------
__global__ __launch_bounds__(32)
void ctc_kernel(const int* __restrict__ y, float* __restrict__ out)
{
    const int b = blockIdx.x, l = threadIdx.x;
    const int lbl = y[b * LBLc + l];
    const int lblp = __shfl_up_sync(0xffffffffu, lbl, 1);
    const bool sk = (l > 0) && (lbl != lblp);
    const float* lp = &g_logp[b][0][0];

    float a0 = (l == 0) ? lp[Vc - 1] : NEGF;
    float a1 = (l == 0) ? lp[lbl]    : NEGF;
    float a2 = NEGF;

    float pb[2], py[2];
    pb[0] = __ldcg(&lp[Vc * 1 + (Vc - 1)]);  py[0] = __ldcg(&lp[Vc * 1 + lbl]);
    pb[1] = __ldcg(&lp[Vc * 2 + (Vc - 1)]);  py[1] = __ldcg(&lp[Vc * 2 + lbl]);

    for (int t = 1; t < Tc; t++) {
        const float lpb = pb[0], lpy = py[0];
        pb[0] = pb[1]; py[0] = py[1];
        if (t + 2 < Tc) {
            pb[1] = __ldcg(&lp[Vc * (t + 2) + (Vc - 1)]);
            py[1] = __ldcg(&lp[Vc * (t + 2) + lbl]);
        }
        float pa1 = __shfl_up_sync(0xffffffffu, a1, 1);
        if (l == 0) pa1 = NEGF;

        float m0 = fmaxf(a0, pa1);
        float n0 = m0 + __logf(__expf(a0 - m0) + __expf(pa1 - m0)) + lpb;

        float s2 = sk ? pa1 : NEGF;
        float m1 = fmaxf(a1, fmaxf(a0, s2));
        float n1 = m1 + __logf(__expf(a1 - m1) + __expf(a0 - m1) +
                               __expf(s2 - m1)) + lpy;

        float n2 = a2;
        if (l == 31) {
            float m2 = fmaxf(a2, a1);
            n2 = m2 + __logf(__expf(a2 - m2) + __expf(a1 - m2)) + lpb;
        }
        a0 = n0; a1 = n1; a2 = n2;
    }

    if (l == 31) {
        float m = fmaxf(a2, a1);
        out[b] = -(m + __logf(__expf(a2 - m) + __expf(a1 - m)));
    }
}

// ---------------------------------------------------------------------------
// Inputs: X, y, Wx, Wh1, Wh2, b, W_fc, b_fc. Output: float[32].
// ---------------------------------------------------------------------------
extern "C" void kernel_launch(void* const* d_in, const int* in_sizes, int n_in,
                              void* d_out, int out_size)
{
    const float* X    = (const float*)d_in[0];
    const int*   y    = (const int*)  d_in[1];
    const float* Wx   = (const float*)d_in[2];
    const float* Wh1  = (const float*)d_in[3];
    const float* Wh2  = (const float*)d_in[4];
    const float* bias = (const float*)d_in[5];
    const float* W_fc = (const float*)d_in[6];
    const float* b_fc = (const float*)d_in[7];
    float* out = (float*)d_out;

    cudaFuncSetAttribute(mdlstm_persist,
                         cudaFuncAttributeMaxDynamicSharedMemorySize, SMEM_BYTES);
    cudaFuncSetAttribute(fc_kernel,
                         cudaFuncAttributeMaxDynamicSharedMemorySize, FC_SMEM);

    init_kernel<<<256, 256>>>();
    mdlstm_persist<<<NCTA, NTHR, SMEM_BYTES>>>(X, Wx, Wh1, Wh2, bias);
    fc_kernel<<<dim3(Tc / FCW, Bc), 128, FC_SMEM>>>(W_fc, b_fc);
    ctc_kernel<<<Bc, 32>>>(y, out);
}